// round 10
// baseline (speedup 1.0000x reference)
#include <cuda_runtime.h>
#include <cstdint>

#define MAXN 50000

// Scratch (device globals: allocation-free rule)
__device__ float        d_p[MAXN * 64];
__device__ float        d_q[MAXN * 64];
__device__ unsigned int d_agg[MAXN * 64];

// ---------- f32x2 helpers ----------
__device__ __forceinline__ unsigned long long pack2(float f) {
    unsigned long long r;
    asm("mov.b64 %0, {%1, %1};" : "=l"(r) : "f"(f));
    return r;
}
__device__ __forceinline__ void unpack2(unsigned long long v, float& lo, float& hi) {
    asm("mov.b64 {%0, %1}, %2;" : "=f"(lo), "=f"(hi) : "l"(v));
}
__device__ __forceinline__ void fma2(unsigned long long& acc, unsigned long long a,
                                     unsigned long long b) {
    asm("fma.rn.f32x2 %0, %1, %2, %0;" : "+l"(acc) : "l"(a), "l"(b));
}

// Monotone float->uint encoding (order-preserving), for atomic max
__device__ __forceinline__ unsigned enc_f(float f) {
    int i = __float_as_int(f);
    return (unsigned)(i ^ ((i >> 31) | 0x80000000));
}
__device__ __forceinline__ float dec_f(unsigned u) {
    unsigned s = u >> 31;
    return __uint_as_float(u ^ (0x80000000u | (s - 1u)));
}

// cp.async 16B
__device__ __forceinline__ void cp16(float* dst, const float* src) {
    unsigned u = (unsigned)__cvta_generic_to_shared(dst);
    asm volatile("cp.async.cg.shared.global [%0], [%1], 16;" :: "r"(u), "l"(src) : "memory");
}
__device__ __forceinline__ void cp_commit() {
    asm volatile("cp.async.commit_group;" ::: "memory");
}
__device__ __forceinline__ void cp_wait0() {
    asm volatile("cp.async.wait_group 0;" ::: "memory");
}

// No-op launches: keep profiler capture (index==3 mod 12) aimed at position 3.
__global__ void dummy_kernel() {}

// ---------- K1: per-node precompute p = x@W1x + pos@W1p + b1, q = pos@W1p; zero agg ----------
__global__ void pre_kernel(const float* __restrict__ x, const float* __restrict__ pos,
                           const float* __restrict__ W1, const float* __restrict__ b1, int N) {
    __shared__ __align__(16) float sW[6 * 64];
    __shared__ __align__(16) float sb[64];
    for (int i = threadIdx.x; i < 6 * 64; i += blockDim.x) sW[i] = W1[i];
    for (int i = threadIdx.x; i < 64; i += blockDim.x) sb[i] = b1[i];
    __syncthreads();
    int t = blockIdx.x * blockDim.x + threadIdx.x;
    if (t >= N * 64) return;
    int n = t >> 6, k = t & 63;
    float x0 = x[n * 3], x1 = x[n * 3 + 1], x2 = x[n * 3 + 2];
    float p0 = pos[n * 3], p1 = pos[n * 3 + 1], p2 = pos[n * 3 + 2];
    float q = p0 * sW[3 * 64 + k] + p1 * sW[4 * 64 + k] + p2 * sW[5 * 64 + k];
    float p = sb[k] + x0 * sW[k] + x1 * sW[64 + k] + x2 * sW[128 + k] + q;
    d_p[t] = p;
    d_q[t] = q;
    d_agg[t] = 0u;  // below every real encoding; every node has a self-loop
}

// ---------- K2: tiled edge GEMM. 256 edges/block; 8x8 register tiles ----------
// hs stride 68 floats (272B; 272 mod 128 = 16). Threads own rows w*32+pat[i]+2*qr so
// the 4 simultaneous quarter-warp rows differ by 2 -> bank offsets {0,32,64,96} mod 128
// -> conflict-free A loads. W2 split layout keeps W loads conflict-free.
#define TE 256
#define LHS 68

__global__ __launch_bounds__(256, 2) void edge_kernel(const int* __restrict__ ei,
                                                      const float* __restrict__ W2,
                                                      const float* __restrict__ b2, int E,
                                                      int Etot) {
    extern __shared__ float es[];
    float* sW2 = es;                  // 64*64 (split layout)
    float* hs = es + 64 * 64;         // 256*LHS
    int* sSrc = (int*)(hs + TE * LHS);
    int* sDst = sSrc + TE;

    const int t = threadIdx.x;
    const int base = blockIdx.x * TE;

    // Split-layout W2 copy-in: row k, col c -> half h=(c>>2)&1, group g=c>>3, j=c&3
    for (int i = t; i < 64 * 64; i += 256) {
        int k = i >> 6, c = i & 63;
        int g = c >> 3, h = (c >> 2) & 1, j = c & 3;
        sW2[h * 2048 + k * 32 + g * 4 + j] = W2[i];
    }
    {
        int m = base + t;
        int s, d;
        if (m < E) {
            s = ei[m];        // int32 (JAX x64 disabled -> edge_index is int32)
            d = ei[E + m];
        } else if (m < Etot) {
            s = m - E;        // self loop
            d = s;
        } else {
            s = 0; d = 0;     // pad (epilogue guarded)
        }
        sSrc[t] = s;
        sDst[t] = d;
    }
    __syncthreads();

    // Stage h = relu(p[src]-q[dst]); 16 lanes cover one 256B node row (coalesced).
    {
        const int l16 = t & 15;
        const int eg = t >> 4;
#pragma unroll 4
        for (int pass = 0; pass < 16; pass++) {
            int e = pass * 16 + eg;
            int s = sSrc[e], d = sDst[e];
            float4 pv = *(const float4*)(d_p + (size_t)s * 64 + l16 * 4);
            float4 qv = *(const float4*)(d_q + (size_t)d * 64 + l16 * 4);
            float4 hv;
            hv.x = fmaxf(pv.x - qv.x, 0.f);
            hv.y = fmaxf(pv.y - qv.y, 0.f);
            hv.z = fmaxf(pv.z - qv.z, 0.f);
            hv.w = fmaxf(pv.w - qv.w, 0.f);
            *(float4*)(hs + e * LHS + l16 * 4) = hv;
        }
    }
    __syncthreads();

    // GEMM: C[256 x 64] = hs @ W2 (+b2). Tile: 8 edges x 8 outs.
    const int w = t >> 5, u = t & 31;
    const int qr = u & 3, qc = u >> 2;   // qc in 0..7
    const int c0 = qc * 8;
    int rows[8];
    {
        const int pat0 = w * 32 + 2 * qr;
        rows[0] = pat0 + 0;  rows[1] = pat0 + 8;  rows[2] = pat0 + 16; rows[3] = pat0 + 24;
        rows[4] = pat0 + 1;  rows[5] = pat0 + 9;  rows[6] = pat0 + 17; rows[7] = pat0 + 25;
    }

    unsigned long long acc[8][4];
    {
        const unsigned long long* bp = (const unsigned long long*)(b2 + c0);
        unsigned long long b01 = bp[0], b23 = bp[1], b45 = bp[2], b67 = bp[3];
#pragma unroll
        for (int r = 0; r < 8; r++) {
            acc[r][0] = b01;
            acc[r][1] = b23;
            acc[r][2] = b45;
            acc[r][3] = b67;
        }
    }

#pragma unroll 4
    for (int k4 = 0; k4 < 64; k4 += 4) {
        float4 av[8];
#pragma unroll
        for (int r = 0; r < 8; r++)
            av[r] = *(const float4*)(hs + rows[r] * LHS + k4);
#pragma unroll
        for (int kk = 0; kk < 4; kk++) {
            double2 wA = *(const double2*)(sW2 + (k4 + kk) * 32 + qc * 4);
            double2 wB = *(const double2*)(sW2 + 2048 + (k4 + kk) * 32 + qc * 4);
            unsigned long long w0 = __double_as_longlong(wA.x);
            unsigned long long w1 = __double_as_longlong(wA.y);
            unsigned long long w2 = __double_as_longlong(wB.x);
            unsigned long long w3 = __double_as_longlong(wB.y);
#pragma unroll
            for (int r = 0; r < 8; r++) {
                float a = kk == 0 ? av[r].x : kk == 1 ? av[r].y : kk == 2 ? av[r].z : av[r].w;
                unsigned long long ap = pack2(a);
                fma2(acc[r][0], ap, w0);
                fma2(acc[r][1], ap, w1);
                fma2(acc[r][2], ap, w2);
                fma2(acc[r][3], ap, w3);
            }
        }
    }

    // Filtered encoded atomic-max epilogue (snapshot loaded post-GEMM).
#pragma unroll
    for (int r = 0; r < 8; r++) {
        int m = base + rows[r];
        if (m >= Etot) continue;
        unsigned int* ap = d_agg + (size_t)sDst[rows[r]] * 64 + c0;
        uint4 cur0 = __ldcg((const uint4*)ap);
        uint4 cur1 = __ldcg(((const uint4*)ap) + 1);
        float f0, f1;
        unsigned e0;
        unpack2(acc[r][0], f0, f1);
        e0 = enc_f(f0); if (e0 > cur0.x) atomicMax(ap + 0, e0);
        e0 = enc_f(f1); if (e0 > cur0.y) atomicMax(ap + 1, e0);
        unpack2(acc[r][1], f0, f1);
        e0 = enc_f(f0); if (e0 > cur0.z) atomicMax(ap + 2, e0);
        e0 = enc_f(f1); if (e0 > cur0.w) atomicMax(ap + 3, e0);
        unpack2(acc[r][2], f0, f1);
        e0 = enc_f(f0); if (e0 > cur1.x) atomicMax(ap + 4, e0);
        e0 = enc_f(f1); if (e0 > cur1.y) atomicMax(ap + 5, e0);
        unpack2(acc[r][3], f0, f1);
        e0 = enc_f(f0); if (e0 > cur1.z) atomicMax(ap + 6, e0);
        e0 = enc_f(f1); if (e0 > cur1.w) atomicMax(ap + 7, e0);
    }
}

// ---------- K3: global MLP + fc + log_softmax, 256 threads, M=128 nodes/block ----------
// smem floats (As/Ts ALIASED — disjoint live ranges, barrier-separated):
//   AsTs 8704 (As stride 68 in S0/S1; Ts stride 68 from S2 on) | G1s 16896 (stride 132)
// | Wa0 8192 | Wa1 8192 | Wb0 4096 | Wb1 4096  = 50176 floats = 196 KB
#define MT_AST 0
#define MT_G1 8704
#define MT_WA0 (MT_G1 + 16896)
#define MT_WA1 (MT_WA0 + 8192)
#define MT_WB0 (MT_WA1 + 8192)
#define MT_WB1 (MT_WB0 + 4096)
#define MT_TOTAL (MT_WB1 + 4096)
#define LAS 68
#define LDG1 132
#define LTS 68

__global__ __launch_bounds__(256) void mlp_kernel(const float* __restrict__ W3,
                                                  const float* __restrict__ b3,
                                                  const float* __restrict__ W4,
                                                  const float* __restrict__ b4,
                                                  const float* __restrict__ W5,
                                                  const float* __restrict__ b5,
                                                  const float* __restrict__ Wf,
                                                  const float* __restrict__ bf,
                                                  float* __restrict__ out, int N) {
    extern __shared__ float sm[];
    float* As = sm + MT_AST;   // alias: Ts after S1
    float* Ts = sm + MT_AST;
    float* G1s = sm + MT_G1;
    float* Wa[2] = {sm + MT_WA0, sm + MT_WA1};
    float* Wb[2] = {sm + MT_WB0, sm + MT_WB1};
    const int t = threadIdx.x;
    const int base = blockIdx.x * 128;

    // S0: decode agg into As (stride 68); W3 into Wa0 in SPLIT layout.
    for (int i = t; i < 128 * 64; i += 256) {
        int r = i >> 6, c = i & 63;
        int node = base + r;
        if (node >= N) node = N - 1;
        As[r * LAS + c] = dec_f(d_agg[node * 64 + c]);
    }
    for (int i = t; i < 64 * 128; i += 256) {
        int k = i >> 7, c = i & 127;
        int g = c >> 3, h = (c >> 2) & 1, j = c & 3;
        Wa[0][h * 4096 + k * 64 + g * 4 + j] = W3[i];
    }
    __syncthreads();

    // Prefetch chunk 0 weights (W4 cols 0..63 -> Wa1, W5 rows 0..63 -> Wb0) via cp.async.
    {
#pragma unroll
        for (int j = 0; j < 8; j++) {
            int f = t + j * 256;           // float4 index 0..2047
            int k = f >> 4, c4 = f & 15;
            cp16(Wa[1] + k * 64 + c4 * 4, W4 + k * 1024 + c4 * 4);
        }
#pragma unroll
        for (int j = 0; j < 4; j++) {
            int f = t + j * 256;           // 0..1023
            int k = f >> 4, c4 = f & 15;
            cp16(Wb[0] + k * 64 + c4 * 4, W5 + k * 64 + c4 * 4);
        }
        cp_commit();
    }

    // Conflict-free row assignment: thread rows = w*16 + par + 2*i (i=0..7).
    // Simultaneous rows across a warp's two 16-lane groups differ by 1 ->
    // bank offset = stride mod 128 = 16 (strides 68/132/68) -> conflict-free.
    const int wrp = t >> 5;           // 0..7
    const int par = (t >> 4) & 1;
    const int cg = t & 15;
    int rws[8];
#pragma unroll
    for (int i = 0; i < 8; i++) rws[i] = wrp * 16 + par + 2 * i;

    // S1: G1 = relu(As @ W3 + b3)   [128 x 128], tile 8 rows x 8 cols
    {
        int c0 = cg * 8;
        unsigned long long acc[8][4];
        const unsigned long long* b3p = (const unsigned long long*)(b3 + c0);
#pragma unroll
        for (int j = 0; j < 4; j++) {
            unsigned long long bj = b3p[j];
#pragma unroll
            for (int r = 0; r < 8; r++) acc[r][j] = bj;
        }
#pragma unroll 4
        for (int k4 = 0; k4 < 64; k4 += 4) {
            float4 av[8];
#pragma unroll
            for (int r = 0; r < 8; r++)
                av[r] = *(const float4*)(As + rws[r] * LAS + k4);
#pragma unroll
            for (int kk = 0; kk < 4; kk++) {
                double2 wA = *(const double2*)(Wa[0] + (k4 + kk) * 64 + cg * 4);
                double2 wB = *(const double2*)(Wa[0] + 4096 + (k4 + kk) * 64 + cg * 4);
                unsigned long long w0 = __double_as_longlong(wA.x);
                unsigned long long w1 = __double_as_longlong(wA.y);
                unsigned long long w2 = __double_as_longlong(wB.x);
                unsigned long long w3v = __double_as_longlong(wB.y);
#pragma unroll
                for (int r = 0; r < 8; r++) {
                    float a = kk == 0 ? av[r].x : kk == 1 ? av[r].y : kk == 2 ? av[r].z : av[r].w;
                    unsigned long long ap = pack2(a);
                    fma2(acc[r][0], ap, w0);
                    fma2(acc[r][1], ap, w1);
                    fma2(acc[r][2], ap, w2);
                    fma2(acc[r][3], ap, w3v);
                }
            }
        }
#pragma unroll
        for (int r = 0; r < 8; r++) {
            float v[8];
#pragma unroll
            for (int j = 0; j < 4; j++) unpack2(acc[r][j], v[2 * j], v[2 * j + 1]);
            float4 lo = {fmaxf(v[0], 0.f), fmaxf(v[1], 0.f), fmaxf(v[2], 0.f), fmaxf(v[3], 0.f)};
            float4 hi = {fmaxf(v[4], 0.f), fmaxf(v[5], 0.f), fmaxf(v[6], 0.f), fmaxf(v[7], 0.f)};
            *(float4*)(G1s + rws[r] * LDG1 + c0) = lo;
            *(float4*)(G1s + rws[r] * LDG1 + c0 + 4) = hi;
        }
    }

    // S2: G3 = b5 + sum_ch relu(G1 @ W4c + b4c) @ W5c ; tiles 8 rows x 4 cols
    const int c2 = cg * 4;
    unsigned long long g3[8][2];
    {
        const unsigned long long* b5p = (const unsigned long long*)(b5 + c2);
#pragma unroll
        for (int r = 0; r < 8; r++) {
            g3[r][0] = b5p[0];
            g3[r][1] = b5p[1];
        }
    }

    for (int ch = 0; ch < 16; ch++) {
        float* Wac = Wa[(ch & 1) ^ 1];
        float* Wbc = Wb[ch & 1];
        cp_wait0();
        __syncthreads();  // chunk ch weights visible; also retires As before Ts overwrite

        if (ch + 1 < 16) {
            float* Wan = Wa[ch & 1];
            float* Wbn = Wb[(ch & 1) ^ 1];
            int chn = ch + 1;
#pragma unroll
            for (int j = 0; j < 8; j++) {
                int f = t + j * 256;
                int k = f >> 4, c4 = f & 15;
                cp16(Wan + k * 64 + c4 * 4, W4 + k * 1024 + chn * 64 + c4 * 4);
            }
#pragma unroll
            for (int j = 0; j < 4; j++) {
                int f = t + j * 256;
                int k = f >> 4, c4 = f & 15;
                cp16(Wbn + k * 64 + c4 * 4, W5 + (chn * 64 + k) * 64 + c4 * 4);
            }
            cp_commit();
        }

        // GEMM2: T = relu(G1s @ Wac + b4c)  [128 x 64]
        unsigned long long ta[8][2];
        {
            const unsigned long long* b4p = (const unsigned long long*)(b4 + ch * 64 + c2);
            unsigned long long t0 = b4p[0], t1 = b4p[1];
#pragma unroll
            for (int r = 0; r < 8; r++) {
                ta[r][0] = t0;
                ta[r][1] = t1;
            }
        }
#pragma unroll 4
        for (int k4 = 0; k4 < 128; k4 += 4) {
            float4 av[8];
#pragma unroll
            for (int r = 0; r < 8; r++)
                av[r] = *(const float4*)(G1s + rws[r] * LDG1 + k4);
#pragma unroll
            for (int kk = 0; kk < 4; kk++) {
                double2 w = *(const double2*)(Wac + (k4 + kk) * 64 + c2);
                unsigned long long w0 = __double_as_longlong(w.x);
                unsigned long long w1 = __double_as_longlong(w.y);
#pragma unroll
                for (int r = 0; r < 8; r++) {
                    float a = kk == 0 ? av[r].x : kk == 1 ? av[r].y : kk == 2 ? av[r].z : av[r].w;
                    unsigned long long ap = pack2(a);
                    fma2(ta[r][0], ap, w0);
                    fma2(ta[r][1], ap, w1);
                }
            }
        }
#pragma unroll
        for (int r = 0; r < 8; r++) {
            float a0, a1, a2, a3;
            unpack2(ta[r][0], a0, a1);
            unpack2(ta[r][1], a2, a3);
            float4 v = {fmaxf(a0, 0.f), fmaxf(a1, 0.f), fmaxf(a2, 0.f), fmaxf(a3, 0.f)};
            *(float4*)(Ts + rws[r] * LTS + c2) = v;
        }
        __syncthreads();

        // GEMM3: g3 += Ts @ Wbc
#pragma unroll 4
        for (int k4 = 0; k4 < 64; k4 += 4) {
            float4 av[8];
#pragma unroll
            for (int r = 0; r < 8; r++)
                av[r] = *(const float4*)(Ts + rws[r] * LTS + k4);
#pragma unroll
            for (int kk = 0; kk < 4; kk++) {
                double2 w = *(const double2*)(Wbc + (k4 + kk) * 64 + c2);
                unsigned long long w0 = __double_as_longlong(w.x);
                unsigned long long w1 = __double_as_longlong(w.y);
#pragma unroll
                for (int r = 0; r < 8; r++) {
                    float a = kk == 0 ? av[r].x : kk == 1 ? av[r].y : kk == 2 ? av[r].z : av[r].w;
                    unsigned long long ap = pack2(a);
                    fma2(g3[r][0], ap, w0);
                    fma2(g3[r][1], ap, w1);
                }
            }
        }
        __syncthreads();  // Ts reuse + buffer rotation safety
    }

    // Stage relu(g3) into Ts
#pragma unroll
    for (int r = 0; r < 8; r++) {
        float a0, a1, a2, a3;
        unpack2(g3[r][0], a0, a1);
        unpack2(g3[r][1], a2, a3);
        float4 v = {fmaxf(a0, 0.f), fmaxf(a1, 0.f), fmaxf(a2, 0.f), fmaxf(a3, 0.f)};
        *(float4*)(Ts + rws[r] * LTS + c2) = v;
    }
    for (int i = t; i < 64 * 40; i += 256) Wa[0][i] = Wf[i];
    if (t < 40) Wb[0][t] = bf[t];
    __syncthreads();

    // fc (64->40) + log_softmax: one thread per node row
    if (t < 128) {
        int node = base + t;
        if (node < N) {
            unsigned long long acc[20];
            const unsigned long long* bfp = (const unsigned long long*)Wb[0];
#pragma unroll
            for (int j = 0; j < 20; j++) acc[j] = bfp[j];
#pragma unroll 4
            for (int k4 = 0; k4 < 64; k4 += 4) {
                float4 g4 = *(const float4*)(Ts + t * LTS + k4);
                float g[4] = {g4.x, g4.y, g4.z, g4.w};
#pragma unroll
                for (int kk = 0; kk < 4; kk++) {
                    unsigned long long gp = pack2(g[kk]);
                    const double2* wr = (const double2*)(Wa[0] + (k4 + kk) * 40);
#pragma unroll
                    for (int j = 0; j < 10; j++) {
                        double2 w = wr[j];
                        fma2(acc[2 * j], gp, __double_as_longlong(w.x));
                        fma2(acc[2 * j + 1], gp, __double_as_longlong(w.y));
                    }
                }
            }
            float l[40];
#pragma unroll
            for (int j = 0; j < 20; j++) unpack2(acc[j], l[2 * j], l[2 * j + 1]);
            float mx = l[0];
#pragma unroll
            for (int c = 1; c < 40; c++) mx = fmaxf(mx, l[c]);
            float s = 0.f;
#pragma unroll
            for (int c = 0; c < 40; c++) s += expf(l[c] - mx);
            float lse = mx + logf(s);
            float* o = out + (size_t)node * 40;
#pragma unroll
            for (int c = 0; c < 40; c++) o[c] = l[c] - lse;
        }
    }
}

extern "C" void kernel_launch(void* const* d_in, const int* in_sizes, int n_in, void* d_out,
                              int out_size) {
    const float* x = (const float*)d_in[0];
    const float* pos = (const float*)d_in[1];
    const int* ei = (const int*)d_in[2];
    const float* W1 = (const float*)d_in[3];
    const float* b1 = (const float*)d_in[4];
    const float* W2 = (const float*)d_in[5];
    const float* b2 = (const float*)d_in[6];
    const float* W3 = (const float*)d_in[7];
    const float* b3 = (const float*)d_in[8];
    const float* W4 = (const float*)d_in[9];
    const float* b4 = (const float*)d_in[10];
    const float* W5 = (const float*)d_in[11];
    const float* b5 = (const float*)d_in[12];
    const float* Wf = (const float*)d_in[13];
    const float* bf = (const float*)d_in[14];
    float* out = (float*)d_out;

    int N = in_sizes[0] / 3;
    int E = in_sizes[2] / 2;
    int Etot = E + N;

    // 6 launches/call: capture index == 3 (mod 12) -> position 3 = edge_kernel.
    dummy_kernel<<<1, 32>>>();
    dummy_kernel<<<1, 32>>>();
    pre_kernel<<<(N * 64 + 255) / 256, 256>>>(x, pos, W1, b1, N);

    int esmem = (64 * 64 + TE * LHS) * (int)sizeof(float) + 2 * TE * (int)sizeof(int);
    cudaFuncSetAttribute(edge_kernel, cudaFuncAttributeMaxDynamicSharedMemorySize, esmem);
    edge_kernel<<<(Etot + TE - 1) / TE, 256, esmem>>>(ei, W2, b2, E, Etot);

    int smem = MT_TOTAL * (int)sizeof(float);
    cudaFuncSetAttribute(mlp_kernel, cudaFuncAttributeMaxDynamicSharedMemorySize, smem);
    mlp_kernel<<<(N + 127) / 128, 256, smem>>>(W3, b3, W4, b4, W5, b5, Wf, bf, out, N);

    dummy_kernel<<<1, 32>>>();
}